// round 7
// baseline (speedup 1.0000x reference)
#include <cuda_runtime.h>
#include <cuda_bf16.h>
#include <stdint.h>

#define BUCKET_SIZE 512
#define G     296            // tiles for pass1/pass3 (2/SM in p1, 1/SM in p3)
#define BLK1  512
#define BLK3  256            // 8 warps
#define WPB3  8
#define MAXNB 8192           // actual nb = 7813
#define MAXN  4194304        // actual n = 4,000,000

__device__ int            g_hist[(size_t)G * MAXNB];           // hist -> clamped bases
__device__ unsigned short g_bkt [MAXN];                        // 8MB per-point bucket
__device__ unsigned       g_cnt [MAXNB];                       // per-bucket totals
__device__ unsigned       g_inv [(size_t)MAXNB * BUCKET_SIZE]; // 16MB slot -> point idx

// ---- Pass 1: hash + u16 bucket + per-block shared-atomic histogram ----
__global__ __launch_bounds__(BLK1) void psh_pass1(
    const float* __restrict__ coords, const int* __restrict__ seps,
    const int* __restrict__ hop_p, int n, int nB, int nb,
    unsigned long long magic_nb, float* __restrict__ out_bucket)
{
    extern __shared__ int sh[];
    int* hist  = sh;        // [nb]
    int* sseps = sh + nb;   // [nB]
    for (int j = threadIdx.x; j < nb; j += BLK1) hist[j] = 0;
    for (int j = threadIdx.x; j < nB; j += BLK1) sseps[j] = seps[j];
    __syncthreads();

    const unsigned hop = (unsigned)hop_p[0];
    const int tile = (n + G - 1) / G;
    const int beg = blockIdx.x * tile;
    const int end = min(n, beg + tile);

    int klo = 0, khi = 0;
    for (int k = 0; k < nB; k++) {
        klo += (sseps[k] <= beg);
        khi += (sseps[k] <= end - 1);
    }

    for (int i = beg + threadIdx.x; i < end; i += BLK1) {
        float x = coords[3*i], y = coords[3*i+1], z = coords[3*i+2];
        unsigned bid = (unsigned)klo;
        for (int k = klo; k < khi; k++) bid += (sseps[k] <= i);
        unsigned vx = (unsigned)(int)floorf(x);
        unsigned vy = (unsigned)(int)floorf(y);
        unsigned vz = (unsigned)(int)floorf(z);
        unsigned h = vx * 73856093u ^ vy * 19349663u ^ vz * 83492791u
                   ^ bid * 2654435761u;
        h += hop;
        unsigned q = (unsigned)__umul64hi((unsigned long long)h, magic_nb);
        unsigned b = h - q * (unsigned)nb;
        out_bucket[i] = (float)b;
        g_bkt[i] = (unsigned short)b;
        atomicAdd(&hist[b], 1);
    }
    __syncthreads();
    for (int j = threadIdx.x; j < nb; j += BLK1)
        g_hist[(size_t)blockIdx.x * nb + j] = hist[j];
}

// ---- Pass 2: coalesced cross-block scan -> CLAMPED exclusive bases; counts ----
__global__ __launch_bounds__(256) void psh_pass2(
    int nb, float* __restrict__ out_counts)
{
    int j = blockIdx.x * 256 + threadIdx.x;
    if (j >= nb) return;
    int carry = 0;
    #pragma unroll 8
    for (int blk = 0; blk < G; blk++) {
        size_t idx = (size_t)blk * nb + j;
        int v = g_hist[idx];
        g_hist[idx] = min(carry, BUCKET_SIZE);  // >=512 -> dropped anyway
        carry += v;
    }
    g_cnt[j] = (unsigned)carry;
    out_counts[j] = (float)carry;
}

// ---- Pass 3: 3-phase warp-private rank, exactly 2 barriers total ----
__global__ __launch_bounds__(BLK3) void psh_pass3(int n, int nb)
{
    extern __shared__ unsigned short cnt[];   // [nb][8] interleaved u16
    unsigned* c32 = (unsigned*)cnt;
    for (int j = threadIdx.x; j < nb * 4; j += BLK3) c32[j] = 0u;
    __syncthreads();

    const int tile = (n + G - 1) / G;
    const int beg = blockIdx.x * tile;
    const int end = min(n, beg + tile);
    const int lane = threadIdx.x & 31;
    const int w    = threadIdx.x >> 5;
    const int sub  = (tile + WPB3 - 1) / WPB3;
    const int wbeg = min(end, beg + w * sub);
    const int wend = min(end, wbeg + sub);

    // -- Phase A: per-warp counts (no barriers; chunk loads are independent) --
    for (int c = wbeg; c < wend; c += 32) {
        int i = c + lane;
        bool v = (i < wend);
        unsigned vm = __ballot_sync(0xffffffffu, v);
        if (v) {
            unsigned b = (unsigned)g_bkt[i];
            unsigned mask = __match_any_sync(vm, b);
            if (lane == __ffs(mask) - 1) {
                int a = (int)b * WPB3 + w;
                cnt[a] = (unsigned short)(cnt[a] + __popc(mask));
            }
        }
    }
    __syncthreads();

    // -- Phase B: counters -> absolute bases (vectorized, 1 uint4 per bucket) --
    for (int j = threadIdx.x; j < nb; j += BLK3) {
        uint4 vv = ((uint4*)cnt)[j];
        unsigned run = (unsigned)g_hist[(size_t)blockIdx.x * nb + j];
        unsigned c0 = vv.x & 0xffffu, c1 = vv.x >> 16;
        unsigned c2 = vv.y & 0xffffu, c3 = vv.y >> 16;
        unsigned c4 = vv.z & 0xffffu, c5 = vv.z >> 16;
        unsigned c6 = vv.w & 0xffffu, c7 = vv.w >> 16;
        unsigned b0 = run; run += c0;  unsigned b1 = run; run += c1;
        unsigned b2 = run; run += c2;  unsigned b3 = run; run += c3;
        unsigned b4 = run; run += c4;  unsigned b5 = run; run += c5;
        unsigned b6 = run; run += c6;  unsigned b7 = run; run += c7;
        vv.x = b0 | (b1 << 16);  vv.y = b2 | (b3 << 16);
        vv.z = b4 | (b5 << 16);  vv.w = b6 | (b7 << 16);
        ((uint4*)cnt)[j] = vv;
    }
    __syncthreads();

    // -- Phase C: re-walk, emit stable slots into inv (4B scatter, L2-hot) --
    for (int c = wbeg; c < wend; c += 32) {
        int i = c + lane;
        bool v = (i < wend);
        unsigned vm = __ballot_sync(0xffffffffu, v);
        if (v) {
            unsigned b = (unsigned)g_bkt[i];
            unsigned mask = __match_any_sync(vm, b);
            int leader = __ffs(mask) - 1;
            unsigned base = 0;
            if (lane == leader) {
                int a = (int)b * WPB3 + w;
                base = cnt[a];
                cnt[a] = (unsigned short)(base + __popc(mask));
            }
            base = __shfl_sync(mask, base, leader);
            unsigned rank = base + __popc(mask & ((1u << lane) - 1u));
            if (rank < BUCKET_SIZE)
                g_inv[(size_t)b * BUCKET_SIZE + rank] = (unsigned)i;
        }
    }
}

// ---- Pass 4: gather — coalesced output writes, random (mostly-L2) reads ----
__global__ __launch_bounds__(256) void psh_pass4(
    const float* __restrict__ coords, int pad_to,
    float* __restrict__ out_coord)
{
    int s = blockIdx.x * 256 + threadIdx.x;
    if (s >= pad_to) return;
    int b = s >> 9;
    int r = s & (BUCKET_SIZE - 1);
    float x = 0.f, y = 0.f, z = 0.f;
    if ((unsigned)r < g_cnt[b]) {
        unsigned i = g_inv[s];
        x = __ldg(&coords[3*i]);
        y = __ldg(&coords[3*i+1]);
        z = __ldg(&coords[3*i+2]);
    }
    out_coord[(size_t)s * 3 + 0] = x;
    out_coord[(size_t)s * 3 + 1] = y;
    out_coord[(size_t)s * 3 + 2] = z;
}

extern "C" void kernel_launch(void* const* d_in, const int* in_sizes, int n_in,
                              void* d_out, int out_size)
{
    const float* coords = (const float*)d_in[0];
    const int*   seps   = (const int*)d_in[1];
    const int*   hop_p  = (const int*)d_in[2];

    const int n  = in_sizes[0] / 3;
    const int nB = in_sizes[1];
    const int pad_to = ((n + BUCKET_SIZE - 1) / BUCKET_SIZE) * BUCKET_SIZE;
    const int nb = pad_to / BUCKET_SIZE;

    float* out_coord  = (float*)d_out;
    float* out_counts = out_coord + (size_t)pad_to * 3;
    float* out_bucket = out_counts + nb;

    unsigned long long magic_nb = (~0ULL) / (unsigned)nb + 1ULL;

    size_t sh1 = (size_t)(nb + 64) * sizeof(int);               // ~31.5 KB
    size_t sh3 = (size_t)nb * WPB3 * sizeof(unsigned short);    // ~125 KB

    static bool attr_set = false;
    if (!attr_set) {
        cudaFuncSetAttribute(psh_pass3,
                             cudaFuncAttributeMaxDynamicSharedMemorySize,
                             MAXNB * WPB3 * (int)sizeof(unsigned short));
        attr_set = true;
    }

    psh_pass1<<<G, BLK1, sh1>>>(coords, seps, hop_p, n, nB, nb,
                                magic_nb, out_bucket);
    psh_pass2<<<(nb + 255) / 256, 256>>>(nb, out_counts);
    psh_pass3<<<G, BLK3, sh3>>>(n, nb);
    psh_pass4<<<(pad_to + 255) / 256, 256>>>(coords, pad_to, out_coord);
}

// round 8
// speedup vs baseline: 1.5447x; 1.5447x over previous
#include <cuda_runtime.h>
#include <cuda_bf16.h>
#include <stdint.h>

#define BUCKET_SIZE 512
#define G1    296               // blocks for pass1 / rank pass
#define WPB   8                 // warps per block
#define W     (G1 * WPB)        // 2368 warp-tiles
#define RG    32                // row-groups for hierarchical scan
#define RPG   ((W + RG - 1) / RG)   // 74
#define MAXNBP 8192             // padded bucket-row stride (actual nbp = 7816)
#define MAXN  4194304

// Scratch (static; no allocations)
__device__ unsigned char  g_cnt8  [(size_t)W * MAXNBP];          // 19.4MB per-warp-tile counts
__device__ unsigned short g_base16[(size_t)W * MAXNBP];          // 38.8MB clamped absolute bases
__device__ unsigned       g_part  [(size_t)RG * MAXNBP];         //  1MB scan partials
__device__ unsigned short g_bkt   [MAXN];                        //  8MB per-point bucket
__device__ unsigned       g_cnt   [MAXNBP];                      // per-bucket totals
__device__ unsigned       g_inv   [(size_t)MAXNBP * BUCKET_SIZE];// 16MB slot -> point idx

// ---- Pass 1: hash + warp-private u8 counting (24 warps/SM, no block barriers in loop) ----
__global__ __launch_bounds__(256) void psh_pass1(
    const float* __restrict__ coords, const int* __restrict__ seps,
    const int* __restrict__ hop_p, int n, int nB, int nb, int nbp, int wtile,
    unsigned long long magic_nb, float* __restrict__ out_bucket)
{
    extern __shared__ unsigned char cnt[];   // [WPB][nbp]
    const int lane = threadIdx.x & 31;
    const int wid  = threadIdx.x >> 5;
    for (int j = threadIdx.x; j < (WPB * nbp) >> 2; j += 256)
        ((unsigned*)cnt)[j] = 0u;
    __syncthreads();
    unsigned char* cw = cnt + wid * nbp;

    const unsigned hop = (unsigned)hop_p[0];
    const int wt  = blockIdx.x * WPB + wid;
    const int beg = wt * wtile;
    const int end = min(n, beg + wtile);

    int klo = 0, khi = 0;
    if (beg < end) {
        for (int k = 0; k < nB; k++) {
            int s = __ldg(&seps[k]);
            klo += (s <= beg);
            khi += (s <= end - 1);
        }
    }

    int i = beg + lane;
    bool v = (i < end);
    float x = 0.f, y = 0.f, z = 0.f;
    if (v) { x = coords[3*i]; y = coords[3*i+1]; z = coords[3*i+2]; }

    for (int c = beg; c < end; c += 32) {
        int ni = i + 32;                       // prefetch next chunk
        bool vn = (ni < end);
        float nx = 0.f, ny = 0.f, nz = 0.f;
        if (vn) { nx = coords[3*ni]; ny = coords[3*ni+1]; nz = coords[3*ni+2]; }

        unsigned vm = __ballot_sync(0xffffffffu, v);
        if (v) {
            unsigned bid = (unsigned)klo;
            for (int k = klo; k < khi; k++) bid += (__ldg(&seps[k]) <= i);
            unsigned vx = (unsigned)(int)floorf(x);
            unsigned vy = (unsigned)(int)floorf(y);
            unsigned vz = (unsigned)(int)floorf(z);
            unsigned h = vx * 73856093u ^ vy * 19349663u ^ vz * 83492791u
                       ^ bid * 2654435761u;
            h += hop;
            unsigned q = (unsigned)__umul64hi((unsigned long long)h, magic_nb);
            unsigned b = h - q * (unsigned)nb;
            out_bucket[i] = (float)b;
            g_bkt[i] = (unsigned short)b;
            unsigned mask = __match_any_sync(vm, b);
            if (lane == __ffs(mask) - 1)
                cw[b] = (unsigned char)(cw[b] + __popc(mask));
        }
        i = ni; v = vn; x = nx; y = ny; z = nz;
    }

    // each warp flushes its own row (u32-coalesced); no barrier needed
    __syncwarp();
    const unsigned* src = (const unsigned*)(cnt + wid * nbp);
    unsigned* dst = (unsigned*)(g_cnt8 + (size_t)wt * nbp);
    for (int j = lane; j < (nbp >> 2); j += 32) dst[j] = src[j];
}

// ---- Scan 2a: 4-bucket-vectorized partial sums per row-group ----
__global__ __launch_bounds__(256) void psh_pass2a(int nbp)
{
    int q  = blockIdx.x * 256 + threadIdx.x;   // group of 4 buckets
    int rg = blockIdx.y;
    if (q >= (nbp >> 2)) return;
    int r0 = rg * RPG, r1 = min(W, r0 + RPG);
    unsigned s0 = 0, s1 = 0, s2 = 0, s3 = 0;
    const unsigned* rows = (const unsigned*)g_cnt8;
    #pragma unroll 8
    for (int r = r0; r < r1; r++) {
        unsigned vv = rows[(size_t)r * (nbp >> 2) + q];
        s0 += vv & 255u; s1 += (vv >> 8) & 255u;
        s2 += (vv >> 16) & 255u; s3 += vv >> 24;
    }
    size_t o = (size_t)rg * nbp + q * 4;
    g_part[o] = s0; g_part[o+1] = s1; g_part[o+2] = s2; g_part[o+3] = s3;
}

// ---- Scan 2b: scan the RG partials per bucket; emit counts ----
__global__ __launch_bounds__(256) void psh_pass2b(
    int nb, int nbp, float* __restrict__ out_counts)
{
    int j = blockIdx.x * 256 + threadIdx.x;
    if (j >= nbp) return;
    unsigned carry = 0;
    #pragma unroll
    for (int rg = 0; rg < RG; rg++) {
        size_t o = (size_t)rg * nbp + j;
        unsigned v = g_part[o];
        g_part[o] = carry;
        carry += v;
    }
    if (j < nb) {
        g_cnt[j] = carry;
        out_counts[j] = (float)carry;
    }
}

// ---- Scan 2c: rescan rows -> clamped u16 absolute bases ----
__global__ __launch_bounds__(256) void psh_pass2c(int nbp)
{
    int q  = blockIdx.x * 256 + threadIdx.x;
    int rg = blockIdx.y;
    if (q >= (nbp >> 2)) return;
    int r0 = rg * RPG, r1 = min(W, r0 + RPG);
    size_t o = (size_t)rg * nbp + q * 4;
    unsigned a0 = g_part[o], a1 = g_part[o+1], a2 = g_part[o+2], a3 = g_part[o+3];
    const unsigned* rows = (const unsigned*)g_cnt8;
    #pragma unroll 4
    for (int r = r0; r < r1; r++) {
        unsigned lo = min(a0, 1024u) | (min(a1, 1024u) << 16);
        unsigned hi = min(a2, 1024u) | (min(a3, 1024u) << 16);
        uint2 pk; pk.x = lo; pk.y = hi;
        *(uint2*)(g_base16 + (size_t)r * nbp + q * 4) = pk;
        unsigned vv = rows[(size_t)r * (nbp >> 2) + q];
        a0 += vv & 255u; a1 += (vv >> 8) & 255u;
        a2 += (vv >> 16) & 255u; a3 += vv >> 24;
    }
}

// ---- Rank pass: warp-private u8 counters + prefetched base; emit inv (4B, L2-hot) ----
__global__ __launch_bounds__(256) void psh_rank(int n, int nbp, int wtile)
{
    extern __shared__ unsigned char cnt[];   // [WPB][nbp]
    const int lane = threadIdx.x & 31;
    const int wid  = threadIdx.x >> 5;
    for (int j = threadIdx.x; j < (WPB * nbp) >> 2; j += 256)
        ((unsigned*)cnt)[j] = 0u;
    __syncthreads();
    unsigned char* cw = cnt + wid * nbp;

    const int wt  = blockIdx.x * WPB + wid;
    const int beg = wt * wtile;
    const int end = min(n, beg + wtile);
    const unsigned short* baserow = g_base16 + (size_t)wt * nbp;

    int i = beg + lane;
    bool v = (i < end);
    unsigned b    = v ? (unsigned)g_bkt[i] : 0u;
    unsigned base = v ? (unsigned)__ldg(&baserow[b]) : 0u;

    for (int c = beg; c < end; c += 32) {
        int ni = i + 32;                      // prefetch next chunk (bkt + base)
        bool vn = (ni < end);
        unsigned bn    = vn ? (unsigned)g_bkt[ni] : 0u;
        unsigned basen = vn ? (unsigned)__ldg(&baserow[bn]) : 0u;

        unsigned vm = __ballot_sync(0xffffffffu, v);
        if (v) {
            unsigned mask = __match_any_sync(vm, b);
            int leader = __ffs(mask) - 1;
            unsigned local = 0;
            if (lane == leader) {
                local = cw[b];
                cw[b] = (unsigned char)(local + __popc(mask));
            }
            local = __shfl_sync(mask, local, leader);
            unsigned rank = base + local + __popc(mask & ((1u << lane) - 1u));
            if (rank < BUCKET_SIZE)
                g_inv[(size_t)b * BUCKET_SIZE + rank] = (unsigned)i;
        }
        i = ni; v = vn; b = bn; base = basen;
    }
}

// ---- Pass 4: gather — coalesced full-sector output writes ----
__global__ __launch_bounds__(256) void psh_pass4(
    const float* __restrict__ coords, int pad_to,
    float* __restrict__ out_coord)
{
    int s = blockIdx.x * 256 + threadIdx.x;
    if (s >= pad_to) return;
    int b = s >> 9;
    int r = s & (BUCKET_SIZE - 1);
    float x = 0.f, y = 0.f, z = 0.f;
    if ((unsigned)r < g_cnt[b]) {
        unsigned i = g_inv[s];
        x = __ldg(&coords[3*i]);
        y = __ldg(&coords[3*i+1]);
        z = __ldg(&coords[3*i+2]);
    }
    out_coord[(size_t)s * 3 + 0] = x;
    out_coord[(size_t)s * 3 + 1] = y;
    out_coord[(size_t)s * 3 + 2] = z;
}

extern "C" void kernel_launch(void* const* d_in, const int* in_sizes, int n_in,
                              void* d_out, int out_size)
{
    const float* coords = (const float*)d_in[0];
    const int*   seps   = (const int*)d_in[1];
    const int*   hop_p  = (const int*)d_in[2];

    const int n  = in_sizes[0] / 3;
    const int nB = in_sizes[1];
    const int pad_to = ((n + BUCKET_SIZE - 1) / BUCKET_SIZE) * BUCKET_SIZE;
    const int nb  = pad_to / BUCKET_SIZE;
    const int nbp = (nb + 7) & ~7;           // padded row stride (mult of 8)
    const int wtile = (n + W - 1) / W;       // 1690 for n=4M

    float* out_coord  = (float*)d_out;
    float* out_counts = out_coord + (size_t)pad_to * 3;
    float* out_bucket = out_counts + nb;

    unsigned long long magic_nb = (~0ULL) / (unsigned)nb + 1ULL;

    size_t shw = (size_t)WPB * nbp;          // 62.5 KB -> 3 blocks/SM

    static bool attr_set = false;
    if (!attr_set) {
        cudaFuncSetAttribute(psh_pass1,
                             cudaFuncAttributeMaxDynamicSharedMemorySize,
                             WPB * MAXNBP);
        cudaFuncSetAttribute(psh_rank,
                             cudaFuncAttributeMaxDynamicSharedMemorySize,
                             WPB * MAXNBP);
        attr_set = true;
    }

    dim3 gscan(((nbp >> 2) + 255) / 256, RG);
    psh_pass1<<<G1, 256, shw>>>(coords, seps, hop_p, n, nB, nb, nbp, wtile,
                                magic_nb, out_bucket);
    psh_pass2a<<<gscan, 256>>>(nbp);
    psh_pass2b<<<(nbp + 255) / 256, 256>>>(nb, nbp, out_counts);
    psh_pass2c<<<gscan, 256>>>(nbp);
    psh_rank<<<G1, 256, shw>>>(n, nbp, wtile);
    psh_pass4<<<(pad_to + 255) / 256, 256>>>(coords, pad_to, out_coord);
}